// round 5
// baseline (speedup 1.0000x reference)
#include <cuda_runtime.h>
#include <cuda_bf16.h>
#include <cstdint>

// Pseudo-random interleaver: out[b, l] = x[b, perm[b, l]]
// B = 1024 rows, L = 16384 elements/row, fp32.
//
// R4: one CTA per row, 512 threads, 64KB smem (3 CTAs/SM).
//  - Stage the x row via cp.async.cg (LDGSTS): no register round-trip, L1 bypass,
//    no mbarrier machinery (the cp.async.bulk path killed the container twice).
//  - Prefetch perm (depth-2, __ldcs) between cp.async issue and wait.
//  - Gather from smem, streaming stores (__stcs) for out.

#define ROW_LEN   16384
#define THREADS   512
#define VEC_ITERS (ROW_LEN / 4 / THREADS)   // 8
#define ROW_BYTES (ROW_LEN * 4)             // 65536

__device__ __forceinline__ uint32_t smem_u32(const void* p) {
    uint32_t a;
    asm("{ .reg .u64 t; cvta.to.shared.u64 t, %1; cvt.u32.u64 %0, t; }"
        : "=r"(a) : "l"(p));
    return a;
}

__global__ __launch_bounds__(THREADS, 3) void interleaver_kernel(
    const float* __restrict__ x,
    const int*   __restrict__ perm,
    float*       __restrict__ out)
{
    extern __shared__ __align__(16) float srow[];   // 16384 floats = 64KB

    const int b   = blockIdx.x;
    const int tid = threadIdx.x;
    const size_t row_off = (size_t)b * ROW_LEN;

    // ---- Stage x row into smem via cp.async (16B per op, L1-bypass) ----
    const float4* __restrict__ x4 = (const float4*)(x + row_off);
    const uint32_t sdst = smem_u32(srow) + (uint32_t)tid * 16u;
    #pragma unroll
    for (int i = 0; i < VEC_ITERS; i++) {
        asm volatile("cp.async.cg.shared.global [%0], [%1], 16;"
                     :: "r"(sdst + (uint32_t)(i * THREADS * 16)),
                        "l"(x4 + tid + i * THREADS)
                     : "memory");
    }
    asm volatile("cp.async.commit_group;" ::: "memory");

    // ---- Prefetch perm (depth 2) while the staging copies are in flight ----
    const int4* __restrict__ p4 = (const int4*)(perm + row_off);
    int4 pa = __ldcs(&p4[tid]);
    int4 pb = __ldcs(&p4[tid + THREADS]);

    // ---- Wait for staging, make it CTA-visible ----
    asm volatile("cp.async.wait_group 0;" ::: "memory");
    __syncthreads();

    // ---- Gather: rotate perm prefetch, random LDS, streaming coalesced stores ----
    float4* __restrict__ o4 = (float4*)(out + row_off);
    #pragma unroll
    for (int i = 0; i < VEC_ITERS; i++) {
        int4 p = pa;
        pa = pb;
        if (i + 2 < VEC_ITERS) pb = __ldcs(&p4[tid + (i + 2) * THREADS]);
        float4 v;
        v.x = srow[p.x];
        v.y = srow[p.y];
        v.z = srow[p.z];
        v.w = srow[p.w];
        __stcs(&o4[tid + i * THREADS], v);
    }
}

extern "C" void kernel_launch(void* const* d_in, const int* in_sizes, int n_in,
                              void* d_out, int out_size)
{
    const float* x    = (const float*)d_in[0];
    const int*   perm = (const int*)d_in[1];
    float*       out  = (float*)d_out;

    const int B = in_sizes[1] / ROW_LEN;          // 1024
    const int smem_bytes = ROW_BYTES;             // 65536

    cudaFuncSetAttribute(interleaver_kernel,
                         cudaFuncAttributeMaxDynamicSharedMemorySize, smem_bytes);

    interleaver_kernel<<<B, THREADS, smem_bytes>>>(x, perm, out);
}